// round 4
// baseline (speedup 1.0000x reference)
#include <cuda_runtime.h>
#include <cuda_fp16.h>
#include <math_constants.h>
#include <cstdint>

// Problem constants: B=512, D=256, C=100000, m=4, lambda=1000
#define MAX_C 100000
#define MAX_B 512
#define DD    256

// ---------------------------------------------------------------------------
// Device scratch (allocation-free rule: __device__ globals)
// ---------------------------------------------------------------------------
__device__ __half g_xh[(size_t)MAX_B * DD];   // fp16(normalized X)
__device__ float  g_xlen[MAX_B];

// ---------------------------------------------------------------------------
// Helpers
// ---------------------------------------------------------------------------
__device__ __forceinline__ uint32_t smem_u32(const void* p) {
    uint32_t a;
    asm("{ .reg .u64 t; cvta.to.shared.u64 t, %1; cvt.u32.u64 %0, t; }" : "=r"(a) : "l"(p));
    return a;
}
__device__ __forceinline__ void cp_async16(uint32_t dst, const void* src) {
    asm volatile("cp.async.cg.shared.global [%0], [%1], 16;" :: "r"(dst), "l"(src));
}
__device__ __forceinline__ void cp_commit() {
    asm volatile("cp.async.commit_group;" ::: "memory");
}
template <int N> __device__ __forceinline__ void cp_wait() {
    asm volatile("cp.async.wait_group %0;" :: "n"(N) : "memory");
}
__device__ __forceinline__ void ldsm_x4(uint32_t& r0, uint32_t& r1, uint32_t& r2, uint32_t& r3,
                                        uint32_t addr) {
    asm volatile("ldmatrix.sync.aligned.m8n8.x4.shared.b16 {%0,%1,%2,%3}, [%4];"
                 : "=r"(r0), "=r"(r1), "=r"(r2), "=r"(r3) : "r"(addr));
}
__device__ __forceinline__ void mma_16816(float& c0, float& c1, float& c2, float& c3,
                                          uint32_t a0, uint32_t a1, uint32_t a2, uint32_t a3,
                                          uint32_t b0, uint32_t b1) {
    asm volatile("mma.sync.aligned.m16n8k16.row.col.f32.f16.f16.f32 "
                 "{%0,%1,%2,%3}, {%4,%5,%6,%7}, {%8,%9}, {%0,%1,%2,%3};"
                 : "+f"(c0), "+f"(c1), "+f"(c2), "+f"(c3)
                 : "r"(a0), "r"(a1), "r"(a2), "r"(a3), "r"(b0), "r"(b1));
}

// ---------------------------------------------------------------------------
// X prep: normalize rows -> fp16. One warp per row, D = 256. (~2us)
// ---------------------------------------------------------------------------
__global__ void xprep_kernel(const float* __restrict__ X, int B) {
    int row  = (blockIdx.x * blockDim.x + threadIdx.x) >> 5;
    int lane = threadIdx.x & 31;
    if (row >= B) return;
    const float* p = X + (size_t)row * DD;
    float4 v0 = *(const float4*)(p + lane * 4);
    float4 v1 = *(const float4*)(p + 128 + lane * 4);
    float s = v0.x*v0.x + v0.y*v0.y + v0.z*v0.z + v0.w*v0.w
            + v1.x*v1.x + v1.y*v1.y + v1.z*v1.z + v1.w*v1.w;
    #pragma unroll
    for (int o = 16; o; o >>= 1) s += __shfl_xor_sync(0xffffffffu, s, o);
    float len = sqrtf(s);
    float inv = 1.0f / len;
    if (lane == 0) g_xlen[row] = len;
    __half2 h0 = __floats2half2_rn(v0.x * inv, v0.y * inv);
    __half2 h1 = __floats2half2_rn(v0.z * inv, v0.w * inv);
    __half2 h2 = __floats2half2_rn(v1.x * inv, v1.y * inv);
    __half2 h3 = __floats2half2_rn(v1.z * inv, v1.w * inv);
    size_t base = (size_t)row * DD;
    *(__half2*)(g_xh + base + lane * 4)           = h0;
    *(__half2*)(g_xh + base + lane * 4 + 2)       = h1;
    *(__half2*)(g_xh + base + 128 + lane * 4)     = h2;
    *(__half2*)(g_xh + base + 128 + lane * 4 + 2) = h3;
}

// ---------------------------------------------------------------------------
// Fused GEMM: loads RAW fp32 W, converts fp32->fp16 in-kernel, accumulates
// per-class-row sum(w^2), normalizes in the epilogue (cos = acc / ||w||).
// CTA 128x128, BK=64, 8 warps (2m x 4n), warp tile 64x32.
// ---------------------------------------------------------------------------
#define BM 128
#define BN 128
#define BK 64
#define NCHUNK (DD / BK)                       // 4

// smem layout (dynamic):
//   [0]      A fp16, stage 0 (128 rows x 128B, swizzled)      16384
//   [16384]  A fp16, stage 1                                  16384
//   [32768]  B fp16 (mma operand, single buffer)              16384
//   [49152]  B fp32 staging (128 rows x 64 floats, linear)    32768
//   [81920]  wlen_inv[128]                                      512
#define A_STAGE_B 16384
#define BH_OFF    32768
#define STG_OFF   49152
#define WLEN_OFF  81920
#define SMEM_TOTAL 82432

// smem xor swizzle for 128-byte fp16 rows: blk' = blk ^ (row % 8)
__device__ __forceinline__ uint32_t sw_off(int row, int blk) {
    return (uint32_t)(row * 128 + ((blk ^ (row & 7)) * 16));
}

__global__ __launch_bounds__(256, 2)
void angle_mma_fused(const float* __restrict__ W, const int* __restrict__ Y,
                     float* __restrict__ out, int C)
{
    extern __shared__ char smem[];
    const uint32_t sbase = smem_u32(smem);
    const int tid  = threadIdx.x;
    const int wid  = tid >> 5;
    const int lane = tid & 31;
    const int wm   = wid >> 2;     // 0..1 : warp m (64 rows)
    const int wn   = wid & 3;      // 0..3 : warp n (32 cols)

    const int bm = blockIdx.x * BM;
    const int bn = blockIdx.y * BN;

    const uint32_t a_st0 = sbase;
    const uint32_t a_st1 = sbase + A_STAGE_B;
    const uint32_t bh    = sbase + BH_OFF;
    const uint32_t stg   = sbase + STG_OFF;
    float* wlen_inv = (float*)(smem + WLEN_OFF);

    // ---- loaders ----
    auto load_a = [&](uint32_t abase, int kc) {
        #pragma unroll
        for (int i = 0; i < 4; i++) {
            int t2 = tid + i * 256;            // 0..1023
            int row = t2 >> 3, blk = t2 & 7;
            cp_async16(abase + sw_off(row, blk),
                       g_xh + (size_t)(bm + row) * DD + kc + blk * 8);
        }
    };
    auto load_bstg = [&](int kc) {
        #pragma unroll
        for (int i = 0; i < 8; i++) {
            int g = tid + i * 256;             // 0..2047
            int row = g >> 4, cb = g & 15;
            int rg = bn + row; if (rg >= C) rg = C - 1;
            cp_async16(stg + g * 16, W + (size_t)rg * DD + kc + cb * 4);
        }
    };

    // ---- prologue: chunk 0 ----
    load_a(a_st0, 0);
    load_bstg(0);
    cp_commit();

    float c[4][4][4];
    #pragma unroll
    for (int mt = 0; mt < 4; mt++)
        #pragma unroll
        for (int nt = 0; nt < 4; nt++)
            #pragma unroll
            for (int q = 0; q < 4; q++) c[mt][nt][q] = 0.f;

    float sumsq[8];
    #pragma unroll
    for (int i = 0; i < 8; i++) sumsq[i] = 0.f;

    // per-lane ldmatrix rows (fixed across chunks)
    const int a_hi = lane >> 4;
    int a_row[4], b_row[2];
    #pragma unroll
    for (int mt = 0; mt < 4; mt++) a_row[mt] = wm * 64 + mt * 16 + (lane & 15);
    #pragma unroll
    for (int bt = 0; bt < 2; bt++) b_row[bt] = wn * 32 + bt * 16 + ((lane >> 3) & 1) * 8 + (lane & 7);

    const int cvt_r0 = tid >> 4;           // base row for cvt phase
    const int cvt_cb = tid & 15;           // col-block (4 floats) within row
    const uint32_t cvt_blk_base = (uint32_t)(cvt_cb >> 1);
    const uint32_t cvt_sub = (uint32_t)(cvt_cb & 1) * 8;

    // ---- main loop ----
    #pragma unroll
    for (int ck = 0; ck < NCHUNK; ck++) {
        cp_wait<0>();
        __syncthreads();            // staging(ck) + A(ck) ready; prev MMA done

        // cvt phase: fp32 staging -> fp16 B operand (+ sumsq), 2 waves of 4
        #pragma unroll
        for (int wv = 0; wv < 2; wv++) {
            float4 v[4];
            #pragma unroll
            for (int j = 0; j < 4; j++) {
                int g = tid + (wv * 4 + j) * 256;
                v[j] = *(const float4*)(smem + STG_OFF + g * 16);
            }
            #pragma unroll
            for (int j = 0; j < 4; j++) {
                const int i = wv * 4 + j;
                sumsq[i] += v[j].x*v[j].x + v[j].y*v[j].y + v[j].z*v[j].z + v[j].w*v[j].w;
                __half2 h0 = __floats2half2_rn(v[j].x, v[j].y);
                __half2 h1 = __floats2half2_rn(v[j].z, v[j].w);
                const int r = cvt_r0 + i * 16;
                uint32_t off = (uint32_t)r * 128 +
                               ((cvt_blk_base ^ (uint32_t)(r & 7)) * 16) + cvt_sub;
                *(uint2*)(smem + BH_OFF + off) =
                    make_uint2(*(uint32_t*)&h0, *(uint32_t*)&h1);
            }
        }
        __syncthreads();            // Bh visible; staging free

        if (ck + 1 < NCHUNK) {
            load_a((ck & 1) ? a_st0 : a_st1, (ck + 1) * BK);
            load_bstg((ck + 1) * BK);
            cp_commit();
        }

        // MMA phase
        const uint32_t abase = (ck & 1) ? a_st1 : a_st0;
        #pragma unroll
        for (int ks = 0; ks < 4; ks++) {
            uint32_t a[4][4], b[2][4];
            #pragma unroll
            for (int mt = 0; mt < 4; mt++)
                ldsm_x4(a[mt][0], a[mt][1], a[mt][2], a[mt][3],
                        abase + sw_off(a_row[mt], ks * 2 + a_hi));
            #pragma unroll
            for (int bt = 0; bt < 2; bt++)
                ldsm_x4(b[bt][0], b[bt][1], b[bt][2], b[bt][3],
                        bh + sw_off(b_row[bt], ks * 2 + a_hi));
            #pragma unroll
            for (int mt = 0; mt < 4; mt++) {
                #pragma unroll
                for (int nt = 0; nt < 4; nt++) {
                    const int bt = nt >> 1, sub = nt & 1;
                    mma_16816(c[mt][nt][0], c[mt][nt][1], c[mt][nt][2], c[mt][nt][3],
                              a[mt][0], a[mt][1], a[mt][2], a[mt][3],
                              b[bt][sub], b[bt][2 + sub]);
                }
            }
        }
    }

    // ---- reduce sumsq -> 1/||w|| per class row (16-lane groups) ----
    #pragma unroll
    for (int i = 0; i < 8; i++) {
        float s = sumsq[i];
        s += __shfl_xor_sync(0xffffffffu, s, 1);
        s += __shfl_xor_sync(0xffffffffu, s, 2);
        s += __shfl_xor_sync(0xffffffffu, s, 4);
        s += __shfl_xor_sync(0xffffffffu, s, 8);
        if ((lane & 15) == 0) wlen_inv[cvt_r0 + i * 16] = rsqrtf(s);
    }
    __syncthreads();

    // ---- epilogue: cos -> feat (+ margin at label) ----
    const float inv_pi     = 1.0f / CUDART_PI_F;
    const float inv_1plamb = 1.0f / 1001.0f;

    #pragma unroll
    for (int mt = 0; mt < 4; mt++) {
        const int r0 = bm + wm * 64 + mt * 16 + (lane >> 2);
        const int r1 = r0 + 8;
        const float xl0 = g_xlen[r0], xl1 = g_xlen[r1];
        const int  lab0 = Y[r0],      lab1 = Y[r1];
        #pragma unroll
        for (int nt = 0; nt < 4; nt++) {
            const int lc  = wn * 32 + nt * 8 + (lane & 3) * 2;   // local col in tile
            const int col = bn + lc;
            if (col >= C) continue;          // col even, C even -> col+1 < C too
            const float wli0 = wlen_inv[lc];
            const float wli1 = wlen_inv[lc + 1];
            #pragma unroll
            for (int half = 0; half < 2; half++) {
                const int   rr  = half ? r1 : r0;
                const float xl  = half ? xl1 : xl0;
                const int   lab = half ? lab1 : lab0;
                float v0 = c[mt][nt][half * 2 + 0] * wli0;
                float v1 = c[mt][nt][half * 2 + 1] * wli1;
                v0 = fminf(fmaxf(v0, -1.0f), 1.0f);
                v1 = fminf(fmaxf(v1, -1.0f), 1.0f);
                float f0 = v0 * xl, f1 = v1 * xl;
                if (col == lab || col + 1 == lab) {
                    const bool second = (col + 1 == lab);
                    float cv = second ? v1 : v0;
                    float c2   = cv * cv;
                    float cosm = 8.0f * c2 * c2 - 8.0f * c2 + 1.0f;
                    float kf   = floorf(4.0f * acosf(cv) * inv_pi);
                    float sign = 1.0f - 2.0f * fmodf(kf, 2.0f);
                    float phi  = sign * cosm - 2.0f * kf;
                    float fm   = second ? f1 : f0;
                    fm += (phi * xl - fm) * inv_1plamb;
                    if (second) f1 = fm; else f0 = fm;
                }
                *(float2*)(out + (size_t)rr * C + col) = make_float2(f0, f1);
            }
        }
    }
}

// ---------------------------------------------------------------------------
// Launch
// ---------------------------------------------------------------------------
extern "C" void kernel_launch(void* const* d_in, const int* in_sizes, int n_in,
                              void* d_out, int out_size)
{
    const float* x = (const float*)d_in[0];
    const float* w = (const float*)d_in[1];
    const int*   y = (const int*)d_in[2];
    float* out     = (float*)d_out;

    const int B = in_sizes[2];            // 512
    const int D = in_sizes[0] / B;        // 256
    const int C = in_sizes[1] / D;        // 100000
    (void)D;

    static bool attr_set = false;
    if (!attr_set) {
        cudaFuncSetAttribute(angle_mma_fused,
                             cudaFuncAttributeMaxDynamicSharedMemorySize, SMEM_TOTAL);
        attr_set = true;
    }

    {
        int wpb = 8;
        xprep_kernel<<<(B + wpb - 1) / wpb, wpb * 32>>>(x, B);
    }

    // grid.x = m tiles (fastest -> adjacent CTAs share the same W n-stripe in L2)
    dim3 grid(B / BM, (C + BN - 1) / BN);
    angle_mma_fused<<<grid, 256, SMEM_TOTAL>>>(w, y, out, C);
}